// round 13
// baseline (speedup 1.0000x reference)
#include <cuda_runtime.h>
#include <cstdint>

// CubicalLayer gather: out[i] = X[indices[i].row * 4096 + indices[i].col]
// X: 4096x4096 fp32 (64MB), indices: 524288 x 2 int32, out: 524288 fp32.
//
// R13 probe: last unexplored sweep corner — MLP=8 per thread (65536 threads,
// 14 warps/SM). 4 int4 index loads -> 8 independent front-batched gathers ->
// 2 float4 stores. Total in-flight transactions unchanged (the proven wall:
// ~60G divergent-transaction/s service rate, DRAM 52%-active random-access
// ceiling); this tests whether halving warp count / doubling per-warp burst
// moves anything. Expected neutral; best-so-far (8.672us, MLP=4) stands
// otherwise.

#define W_SHIFT 12   // table row stride 4096

__global__ void __launch_bounds__(256) cubical_gather_kernel(
    const float* __restrict__ X,
    const int4* __restrict__ idx4,   // indices as int4: {r0,c0,r1,c1}
    float4* __restrict__ out4,
    int n_vec8)                       // number of 8-output work items
{
    int t = blockIdx.x * blockDim.x + threadIdx.x;
    if (t >= n_vec8) return;

    // Four int4 loads = 8 (row,col) pairs for outputs [8t .. 8t+7]
    int4 p0 = __ldg(&idx4[4 * t]);
    int4 p1 = __ldg(&idx4[4 * t + 1]);
    int4 p2 = __ldg(&idx4[4 * t + 2]);
    int4 p3 = __ldg(&idx4[4 * t + 3]);

    int o0 = (p0.x << W_SHIFT) + p0.y;
    int o1 = (p0.z << W_SHIFT) + p0.w;
    int o2 = (p1.x << W_SHIFT) + p1.y;
    int o3 = (p1.z << W_SHIFT) + p1.w;
    int o4 = (p2.x << W_SHIFT) + p2.y;
    int o5 = (p2.z << W_SHIFT) + p2.w;
    int o6 = (p3.x << W_SHIFT) + p3.y;
    int o7 = (p3.z << W_SHIFT) + p3.w;

    float4 a, b;
    a.x = __ldg(X + o0);
    a.y = __ldg(X + o1);
    a.z = __ldg(X + o2);
    a.w = __ldg(X + o3);
    b.x = __ldg(X + o4);
    b.y = __ldg(X + o5);
    b.z = __ldg(X + o6);
    b.w = __ldg(X + o7);

    out4[2 * t]     = a;
    out4[2 * t + 1] = b;
}

extern "C" void kernel_launch(void* const* d_in, const int* in_sizes, int n_in,
                              void* d_out, int out_size)
{
    const float* X   = (const float*)d_in[0];   // 4096*4096 fp32
    const int*   idx = (const int*)d_in[1];     // N_IDX*2 int32

    int n_out  = out_size;        // 524288 fp32 elements
    int n_vec8 = n_out / 8;       // 65536 work items of 8 outputs

    int threads = 256;
    int blocks  = (n_vec8 + threads - 1) / threads;   // 256

    cubical_gather_kernel<<<blocks, threads>>>(
        X, (const int4*)idx, (float4*)d_out, n_vec8);
}